// round 13
// baseline (speedup 1.0000x reference)
#include <cuda_runtime.h>
#include <cuda_bf16.h>
#include <math.h>

// Problem constants
#define BB 8
#define NN 1024
#define DD 512
#define HH 8
#define HD 64
#define HB (HH * BB)       // 64
#define MM (BB * NN)       // 8192
#define TOPK 32

// ---------------- scratch (device globals: no allocations allowed) ----------------
__device__ float g_Qp[(size_t)HB * NN * HD];   // 16 MB, head-major packed [hb, n, d]
__device__ float g_Kp[(size_t)HB * NN * HD];   // 16 MB
__device__ float g_Vp[(size_t)HB * NN * HD];   // 16 MB
__device__ float g_S [(size_t)HB * NN * NN];   // 256 MB scores
__device__ float g_Op[(size_t)HB * NN * HD];   // 16 MB attention output (head-major)
__device__ float g_X [(size_t)MM * DD];        // 16 MB after LN1
__device__ float g_H [(size_t)MM * DD];        // 16 MB relu hidden
__device__ float g_F [(size_t)MM * DD];        // 16 MB FF output

// ---------------- fp32 GEMM:  C = op( A[M,K] @ W[K,Ndim] + bias ) ----------------
// grid = (Ndim/128, M/128), block = 256 threads, 128x128 tile, 8x8 per thread, BK=16
__global__ void gemm_kernel(const float* __restrict__ A, const float* __restrict__ W,
                            const float* __restrict__ bias, float* __restrict__ C,
                            int Kdim, int Ndim, float scale, int relu, int head_major)
{
    const int row0 = blockIdx.y * 128;
    const int col0 = blockIdx.x * 128;

    __shared__ float As[16][128];   // As[k][m]
    __shared__ float Bs[16][128];   // Bs[k][n]

    const int tid = threadIdx.x;
    const int tx = tid & 15;        // col group: cols tx*8 .. tx*8+7
    const int ty = tid >> 4;        // row group: rows ty*8 .. ty*8+7

    // A-load mapping (2 float4 per thread, transposed scatter into As)
    const int ra0 = tid >> 2;              // 0..63
    const int ca  = (tid & 3) << 2;        // 0,4,8,12
    // W-load mapping (2 float4 per thread, straight rows into Bs)
    const int wr0 = tid >> 5;              // 0..7
    const int wcc = (tid & 31) << 2;       // 0..124

    float acc[8][8] = {};

    for (int kt = 0; kt < Kdim; kt += 16) {
        float4 av0 = *(const float4*)(A + (size_t)(row0 + ra0)      * Kdim + kt + ca);
        float4 av1 = *(const float4*)(A + (size_t)(row0 + ra0 + 64) * Kdim + kt + ca);
        float4 wv0 = *(const float4*)(W + (size_t)(kt + wr0)     * Ndim + col0 + wcc);
        float4 wv1 = *(const float4*)(W + (size_t)(kt + wr0 + 8) * Ndim + col0 + wcc);
        __syncthreads();   // previous compute done before overwriting smem
        As[ca + 0][ra0] = av0.x; As[ca + 1][ra0] = av0.y;
        As[ca + 2][ra0] = av0.z; As[ca + 3][ra0] = av0.w;
        As[ca + 0][ra0 + 64] = av1.x; As[ca + 1][ra0 + 64] = av1.y;
        As[ca + 2][ra0 + 64] = av1.z; As[ca + 3][ra0 + 64] = av1.w;
        *(float4*)&Bs[wr0][wcc]     = wv0;
        *(float4*)&Bs[wr0 + 8][wcc] = wv1;
        __syncthreads();
#pragma unroll
        for (int kk = 0; kk < 16; ++kk) {
            float a[8], b[8];
            *(float4*)(a)     = *(const float4*)&As[kk][ty * 8];
            *(float4*)(a + 4) = *(const float4*)&As[kk][ty * 8 + 4];
            *(float4*)(b)     = *(const float4*)&Bs[kk][tx * 8];
            *(float4*)(b + 4) = *(const float4*)&Bs[kk][tx * 8 + 4];
#pragma unroll
            for (int i = 0; i < 8; ++i)
#pragma unroll
                for (int j = 0; j < 8; ++j)
                    acc[i][j] = fmaf(a[i], b[j], acc[i][j]);
        }
    }

#pragma unroll
    for (int i = 0; i < 8; ++i) {
        const int row = row0 + ty * 8 + i;
#pragma unroll
        for (int j = 0; j < 8; ++j) {
            const int col = col0 + tx * 8 + j;
            float v = (acc[i][j] + bias[col]) * scale;
            if (relu) v = fmaxf(v, 0.0f);
            if (head_major) {
                const int h = col >> 6, d = col & 63;
                const int b = row >> 10, n = row & 1023;   // N = 1024
                C[(((size_t)(h * BB + b) * NN) + n) * HD + d] = v;
            } else {
                C[(size_t)row * Ndim + col] = v;
            }
        }
    }
}

// ---------------- batched scores: S[hb,q,k] = Q[hb,q,:] . K[hb,k,:] ----------------
// grid = (8 kn-tiles, 8 qn-tiles, 64 hb), block = 256, 128x128 tile, 8x8/thread, BK=16
__global__ void scores_kernel(const float* __restrict__ Qp, const float* __restrict__ Kp,
                              float* __restrict__ S)
{
    const int hb = blockIdx.z;
    const int q0 = blockIdx.y * 128;
    const int k0 = blockIdx.x * 128;
    const float* Qb = Qp + (size_t)hb * NN * HD;
    const float* Kb = Kp + (size_t)hb * NN * HD;

    __shared__ float Qs[16][128];   // Qs[d][q]
    __shared__ float Ks[16][128];   // Ks[d][k]

    const int tid = threadIdx.x;
    const int tx = tid & 15;
    const int ty = tid >> 4;
    const int ra0 = tid >> 2;              // 0..63
    const int ca  = (tid & 3) << 2;        // 0,4,8,12

    float acc[8][8] = {};

    for (int kt = 0; kt < HD; kt += 16) {
        float4 qv0 = *(const float4*)(Qb + (size_t)(q0 + ra0)      * HD + kt + ca);
        float4 qv1 = *(const float4*)(Qb + (size_t)(q0 + ra0 + 64) * HD + kt + ca);
        float4 kv0 = *(const float4*)(Kb + (size_t)(k0 + ra0)      * HD + kt + ca);
        float4 kv1 = *(const float4*)(Kb + (size_t)(k0 + ra0 + 64) * HD + kt + ca);
        __syncthreads();
        Qs[ca + 0][ra0] = qv0.x; Qs[ca + 1][ra0] = qv0.y;
        Qs[ca + 2][ra0] = qv0.z; Qs[ca + 3][ra0] = qv0.w;
        Qs[ca + 0][ra0 + 64] = qv1.x; Qs[ca + 1][ra0 + 64] = qv1.y;
        Qs[ca + 2][ra0 + 64] = qv1.z; Qs[ca + 3][ra0 + 64] = qv1.w;
        Ks[ca + 0][ra0] = kv0.x; Ks[ca + 1][ra0] = kv0.y;
        Ks[ca + 2][ra0] = kv0.z; Ks[ca + 3][ra0] = kv0.w;
        Ks[ca + 0][ra0 + 64] = kv1.x; Ks[ca + 1][ra0 + 64] = kv1.y;
        Ks[ca + 2][ra0 + 64] = kv1.z; Ks[ca + 3][ra0 + 64] = kv1.w;
        __syncthreads();
#pragma unroll
        for (int kk = 0; kk < 16; ++kk) {
            float a[8], b[8];
            *(float4*)(a)     = *(const float4*)&Qs[kk][ty * 8];
            *(float4*)(a + 4) = *(const float4*)&Qs[kk][ty * 8 + 4];
            *(float4*)(b)     = *(const float4*)&Ks[kk][tx * 8];
            *(float4*)(b + 4) = *(const float4*)&Ks[kk][tx * 8 + 4];
#pragma unroll
            for (int i = 0; i < 8; ++i)
#pragma unroll
                for (int j = 0; j < 8; ++j)
                    acc[i][j] = fmaf(a[i], b[j], acc[i][j]);
        }
    }

#pragma unroll
    for (int i = 0; i < 8; ++i) {
        const int qn = q0 + ty * 8 + i;
        float* srow = S + ((size_t)hb * NN + qn) * NN + k0 + tx * 8;
        *(float4*)(srow)     = make_float4(acc[i][0], acc[i][1], acc[i][2], acc[i][3]);
        *(float4*)(srow + 4) = make_float4(acc[i][4], acc[i][5], acc[i][6], acc[i][7]);
    }
}

// ---------------- exact top-32 + softmax + sparse attn@V (radix-256 select) ----------------
// grid = (N, HB), block = 256. One query row per block.
__device__ __forceinline__ float key_to_val(unsigned k) {
    unsigned u = (k & 0x80000000u) ? (k & 0x7fffffffu) : ~k;
    return __uint_as_float(u);
}

__global__ void topk_attn_kernel(const float* __restrict__ S, const float* __restrict__ Vp,
                                 float* __restrict__ Op)
{
    const int qn = blockIdx.x;
    const int hb = blockIdx.y;
    const int tid = threadIdx.x;   // 256
    const float* srow = S + ((size_t)hb * NN + qn) * NN;

    __shared__ unsigned skey[NN];
    __shared__ unsigned hist[256];
    __shared__ unsigned kred[8];
    __shared__ int      sh_digit, sh_need;
    __shared__ int      nsel, neq;
    __shared__ int      idxs[TOPK];
    __shared__ float    ws[TOPK];
    __shared__ int      eqidx[64];
    __shared__ float    mxsh, invsh;
    __shared__ float    vacc[4][HD];

    // load row, build keys, track max key
    unsigned lmk = 0;
    for (int i = tid; i < NN; i += 256) {
        unsigned u = __float_as_uint(srow[i]);
        unsigned k = (u & 0x80000000u) ? ~u : (u | 0x80000000u);
        skey[i] = k;
        lmk = max(lmk, k);
    }
#pragma unroll
    for (int o = 16; o; o >>= 1) lmk = max(lmk, __shfl_xor_sync(0xffffffffu, lmk, o));
    if ((tid & 31) == 0) kred[tid >> 5] = lmk;
    if (tid == 0) { nsel = 0; neq = 0; }
    __syncthreads();
    if (tid == 0) {
        unsigned m = 0;
#pragma unroll
        for (int w = 0; w < 8; ++w) m = max(m, kred[w]);
        mxsh = key_to_val(m);
    }

    // 4-pass radix-256 selection of the 32nd-largest key
    unsigned pfx = 0;
    int need = TOPK;
#pragma unroll
    for (int pass = 0; pass < 4; ++pass) {
        const int shift = 24 - 8 * pass;
        hist[tid] = 0;          // blockDim == 256
        __syncthreads();
        for (int i = tid; i < NN; i += 256) {
            const unsigned k = skey[i];
            const bool match = (pass == 0) || ((k >> (shift + 8)) == pfx);
            if (match) atomicAdd(&hist[(k >> shift) & 255], 1u);
        }
        __syncthreads();
        if (tid < 32) {
            const int base = tid << 3;
            int loc[8];
            int lsum = 0;
#pragma unroll
            for (int j = 0; j < 8; ++j) { loc[j] = (int)hist[base + j]; lsum += loc[j]; }
            // suffix sum across lanes: suf = sum over lanes >= tid
            int suf = lsum;
#pragma unroll
            for (int o = 1; o < 32; o <<= 1) {
                int v = __shfl_down_sync(0xffffffffu, suf, o);
                if (tid + o < 32) suf += v;
            }
            int sufnext = __shfl_down_sync(0xffffffffu, suf, 1);
            if (tid == 31) sufnext = 0;
            if (suf >= need && sufnext < need) {
                int acc = sufnext;
                int digit = 0;
#pragma unroll
                for (int j = 7; j >= 0; --j) {
                    acc += loc[j];
                    if (acc >= need) { digit = j; break; }
                }
                sh_digit = base + digit;
                sh_need  = need - (acc - loc[digit]);   // #tied-at-boundary to keep
            }
        }
        __syncthreads();
        pfx = (pfx << 8) | (unsigned)sh_digit;
        need = sh_need;
        __syncthreads();
    }
    const unsigned tau = pfx;   // exact key of the 32nd-largest; take `need` ties by index

    const float mx = mxsh;
    // gather: strictly-greater always selected; equals collected for index-tiebreak
    for (int i = tid; i < NN; i += 256) {
        const unsigned k = skey[i];
        if (k > tau) {
            int p = atomicAdd(&nsel, 1);
            idxs[p] = i;
            ws[p] = expf(key_to_val(k) - mx);
        } else if (k == tau) {
            int p = atomicAdd(&neq, 1);
            if (p < 64) eqidx[p] = i;
        }
    }
    __syncthreads();
    if (tid == 0) {
        const int g = nsel;                 // == TOPK - need
        int e = neq; if (e > 64) e = 64;
        // insertion sort equals by index ascending (e is tiny, usually 1)
        for (int a = 1; a < e; ++a) {
            int v = eqidx[a]; int p2 = a - 1;
            while (p2 >= 0 && eqidx[p2] > v) { eqidx[p2 + 1] = eqidx[p2]; --p2; }
            eqidx[p2 + 1] = v;
        }
        const float wt = expf(key_to_val(tau) - mx);
        for (int a = 0; a < need; ++a) {
            idxs[g + a] = eqidx[a];
            ws[g + a] = wt;
        }
        float wsum = 0.0f;
        for (int a = 0; a < TOPK; ++a) wsum += ws[a];
        invsh = 1.0f / wsum;
    }
    __syncthreads();

    // attn @ V: 4 groups of 64 threads, each group accumulates 8 selected rows
    const float* vb = Vp + (size_t)hb * NN * HD;
    const int d = tid & 63;
    const int grp = tid >> 6;        // 0..3
    {
        float acc = 0.0f;
#pragma unroll
        for (int j = 0; j < 8; ++j) {
            const int sel = (grp << 3) + j;
            acc = fmaf(ws[sel], vb[(size_t)idxs[sel] * HD + d], acc);
        }
        vacc[grp][d] = acc;
    }
    __syncthreads();
    if (tid < HD) {
        const float inv = invsh;
        float acc = vacc[0][tid] + vacc[1][tid] + vacc[2][tid] + vacc[3][tid];
        Op[((size_t)hb * NN + qn) * HD + tid] = acc * inv;
    }
}

// ---------------- residual add + LayerNorm ----------------
// grid = M (8192), block = 256. add is either head-major packed [hb,n,d] or plain [m, D].
__global__ void addnorm_kernel(const float* __restrict__ base, const float* __restrict__ add,
                               const float* __restrict__ gamma, const float* __restrict__ beta,
                               float* __restrict__ out, int add_head_major)
{
    const int m = blockIdx.x;
    const int b = m >> 10, n = m & 1023;
    const int tid = threadIdx.x;   // 256

    __shared__ float buf[DD];
    __shared__ float r1[8], r2[8];
    __shared__ float stats[2];

    float s1 = 0.0f, s2 = 0.0f;
    for (int j = tid; j < DD; j += 256) {
        float av;
        if (add_head_major) {
            const int h = j >> 6, d = j & 63;
            av = add[(((size_t)(h * BB + b) * NN) + n) * HD + d];
        } else {
            av = add[(size_t)m * DD + j];
        }
        const float v = base[(size_t)m * DD + j] + av;
        buf[j] = v;
        s1 += v;
        s2 += v * v;
    }
#pragma unroll
    for (int o = 16; o; o >>= 1) {
        s1 += __shfl_xor_sync(0xffffffffu, s1, o);
        s2 += __shfl_xor_sync(0xffffffffu, s2, o);
    }
    if ((tid & 31) == 0) { r1[tid >> 5] = s1; r2[tid >> 5] = s2; }
    __syncthreads();
    if (tid == 0) {
        float t1 = 0.0f, t2 = 0.0f;
        for (int w = 0; w < 8; ++w) { t1 += r1[w]; t2 += r2[w]; }
        const float mu = t1 / (float)DD;
        const float var = t2 / (float)DD - mu * mu;
        stats[0] = mu;
        stats[1] = rsqrtf(var + 1e-5f);
    }
    __syncthreads();
    const float mu = stats[0], ivs = stats[1];
    for (int j = tid; j < DD; j += 256)
        out[(size_t)m * DD + j] = (buf[j] - mu) * ivs * gamma[j] + beta[j];
}

// ---------------- launch ----------------
extern "C" void kernel_launch(void* const* d_in, const int* in_sizes, int n_in,
                              void* d_out, int out_size)
{
    const float* src = (const float*)d_in[0];
    const float* tgt = (const float*)d_in[1];
    const float* Wq  = (const float*)d_in[2];
    const float* bq  = (const float*)d_in[3];
    const float* Wk  = (const float*)d_in[4];
    const float* bk  = (const float*)d_in[5];
    const float* Wv  = (const float*)d_in[6];
    const float* bv  = (const float*)d_in[7];
    const float* W1  = (const float*)d_in[8];
    const float* b1  = (const float*)d_in[9];
    const float* W2  = (const float*)d_in[10];
    const float* b2  = (const float*)d_in[11];
    const float* g1  = (const float*)d_in[12];
    const float* be1 = (const float*)d_in[13];
    const float* g2  = (const float*)d_in[14];
    const float* be2 = (const float*)d_in[15];
    float* out = (float*)d_out;

    float *Qp, *Kp, *Vp, *S, *Op, *X, *Hh, *F;
    cudaGetSymbolAddress((void**)&Qp, g_Qp);
    cudaGetSymbolAddress((void**)&Kp, g_Kp);
    cudaGetSymbolAddress((void**)&Vp, g_Vp);
    cudaGetSymbolAddress((void**)&S,  g_S);
    cudaGetSymbolAddress((void**)&Op, g_Op);
    cudaGetSymbolAddress((void**)&X,  g_X);
    cudaGetSymbolAddress((void**)&Hh, g_H);
    cudaGetSymbolAddress((void**)&F,  g_F);

    const float qscale = 0.04419417382415922f;   // 1/sqrt(512)

    dim3 gproj(DD / 128, MM / 128);   // (4, 64)

    // QKV projections (head-major packed outputs)
    gemm_kernel<<<gproj, 256>>>(tgt, Wq, bq, Qp, DD, DD, qscale, 0, 1);
    gemm_kernel<<<gproj, 256>>>(src, Wk, bk, Kp, DD, DD, 1.0f,   0, 1);
    gemm_kernel<<<gproj, 256>>>(src, Wv, bv, Vp, DD, DD, 1.0f,   0, 1);

    // scores
    scores_kernel<<<dim3(NN / 128, NN / 128, HB), 256>>>(Qp, Kp, S);

    // exact top-32 + softmax + sparse attn @ V (radix select)
    topk_attn_kernel<<<dim3(NN, HB), 256>>>(S, Vp, Op);

    // residual + LN1
    addnorm_kernel<<<MM, 256>>>(tgt, Op, g1, be1, X, 1);

    // feed-forward
    gemm_kernel<<<gproj, 256>>>(X,  W1, b1, Hh, DD, DD, 1.0f, 1, 0);
    gemm_kernel<<<gproj, 256>>>(Hh, W2, b2, F,  DD, DD, 1.0f, 0, 0);

    // residual + LN2 -> output
    addnorm_kernel<<<MM, 256>>>(X, F, g2, be2, out, 0);
}

// round 14
// speedup vs baseline: 1.1161x; 1.1161x over previous
#include <cuda_runtime.h>
#include <cuda_bf16.h>
#include <math.h>

// Problem constants
#define BB 8
#define NN 1024
#define DD 512
#define HH 8
#define HD 64
#define HB (HH * BB)       // 64
#define MM (BB * NN)       // 8192
#define TOPK 32

// ---------------- scratch (device globals: no allocations allowed) ----------------
__device__ float g_Qp[(size_t)HB * NN * HD];   // 16 MB, head-major packed [hb, n, d]
__device__ float g_Kp[(size_t)HB * NN * HD];   // 16 MB
__device__ float g_Vp[(size_t)HB * NN * HD];   // 16 MB
__device__ float g_S [(size_t)HB * NN * NN];   // 256 MB scores
__device__ float g_Op[(size_t)HB * NN * HD];   // 16 MB attention output (head-major)
__device__ float g_X [(size_t)MM * DD];        // 16 MB after LN1
__device__ float g_H [(size_t)MM * DD];        // 16 MB relu hidden
__device__ float g_F [(size_t)MM * DD];        // 16 MB FF output

// ---------------- fp32 GEMM (64x64 tile, 4x4/thread) for D=512 matrices ----------------
// grid = (Ndim/64, M/64), block = 256 threads, BK=16
__global__ void gemm_kernel(const float* __restrict__ A, const float* __restrict__ W,
                            const float* __restrict__ bias, float* __restrict__ C,
                            int Kdim, float scale, int relu, int head_major)
{
    const int Ndim = gridDim.x * 64;
    const int row0 = blockIdx.y * 64;
    const int col0 = blockIdx.x * 64;

    __shared__ float As[16][64];
    __shared__ float Bs[16][64];

    const int tid = threadIdx.x;
    const int tx = tid & 15;
    const int ty = tid >> 4;

    const int lr = tid >> 2;             // 0..63 (A tile row)
    const int lc = (tid & 3) << 2;       // 0,4,8,12
    const int wr = tid >> 4;             // 0..15 (W tile row)
    const int wc = (tid & 15) << 2;      // 0..60

    float acc[4][4] = {};

    for (int kt = 0; kt < Kdim; kt += 16) {
        float4 av = *(const float4*)(A + (size_t)(row0 + lr) * Kdim + kt + lc);
        float4 wv = *(const float4*)(W + (size_t)(kt + wr) * Ndim + col0 + wc);
        __syncthreads();
        As[lc + 0][lr] = av.x;
        As[lc + 1][lr] = av.y;
        As[lc + 2][lr] = av.z;
        As[lc + 3][lr] = av.w;
        *(float4*)&Bs[wr][wc] = wv;
        __syncthreads();
#pragma unroll
        for (int kk = 0; kk < 16; ++kk) {
            float a[4], b[4];
#pragma unroll
            for (int i = 0; i < 4; ++i) a[i] = As[kk][(ty << 2) + i];
#pragma unroll
            for (int j = 0; j < 4; ++j) b[j] = Bs[kk][(tx << 2) + j];
#pragma unroll
            for (int i = 0; i < 4; ++i)
#pragma unroll
                for (int j = 0; j < 4; ++j)
                    acc[i][j] = fmaf(a[i], b[j], acc[i][j]);
        }
    }

#pragma unroll
    for (int i = 0; i < 4; ++i) {
        const int row = row0 + (ty << 2) + i;
#pragma unroll
        for (int j = 0; j < 4; ++j) {
            const int col = col0 + (tx << 2) + j;
            float v = (acc[i][j] + bias[col]) * scale;
            if (relu) v = fmaxf(v, 0.0f);
            if (head_major) {
                const int h = col >> 6, d = col & 63;
                const int b = row >> 10, n = row & 1023;   // N = 1024
                C[(((size_t)(h * BB + b) * NN) + n) * HD + d] = v;
            } else {
                C[(size_t)row * Ndim + col] = v;
            }
        }
    }
}

// ---------------- batched scores (128x128 tile, 8x8/thread): S[hb,q,k] = Q.K ----------------
// grid = (8, 8, 64), block = 256, BK=16
__global__ void scores_kernel(const float* __restrict__ Qp, const float* __restrict__ Kp,
                              float* __restrict__ S)
{
    const int hb = blockIdx.z;
    const int q0 = blockIdx.y * 128;
    const int k0 = blockIdx.x * 128;
    const float* Qb = Qp + (size_t)hb * NN * HD;
    const float* Kb = Kp + (size_t)hb * NN * HD;

    __shared__ float Qs[16][128];   // Qs[d][q]
    __shared__ float Ks[16][128];   // Ks[d][k]

    const int tid = threadIdx.x;
    const int tx = tid & 15;
    const int ty = tid >> 4;
    const int ra0 = tid >> 2;              // 0..63
    const int ca  = (tid & 3) << 2;        // 0,4,8,12

    float acc[8][8] = {};

    for (int kt = 0; kt < HD; kt += 16) {
        float4 qv0 = *(const float4*)(Qb + (size_t)(q0 + ra0)      * HD + kt + ca);
        float4 qv1 = *(const float4*)(Qb + (size_t)(q0 + ra0 + 64) * HD + kt + ca);
        float4 kv0 = *(const float4*)(Kb + (size_t)(k0 + ra0)      * HD + kt + ca);
        float4 kv1 = *(const float4*)(Kb + (size_t)(k0 + ra0 + 64) * HD + kt + ca);
        __syncthreads();
        Qs[ca + 0][ra0] = qv0.x; Qs[ca + 1][ra0] = qv0.y;
        Qs[ca + 2][ra0] = qv0.z; Qs[ca + 3][ra0] = qv0.w;
        Qs[ca + 0][ra0 + 64] = qv1.x; Qs[ca + 1][ra0 + 64] = qv1.y;
        Qs[ca + 2][ra0 + 64] = qv1.z; Qs[ca + 3][ra0 + 64] = qv1.w;
        Ks[ca + 0][ra0] = kv0.x; Ks[ca + 1][ra0] = kv0.y;
        Ks[ca + 2][ra0] = kv0.z; Ks[ca + 3][ra0] = kv0.w;
        Ks[ca + 0][ra0 + 64] = kv1.x; Ks[ca + 1][ra0 + 64] = kv1.y;
        Ks[ca + 2][ra0 + 64] = kv1.z; Ks[ca + 3][ra0 + 64] = kv1.w;
        __syncthreads();
#pragma unroll
        for (int kk = 0; kk < 16; ++kk) {
            float a[8], b[8];
            *(float4*)(a)     = *(const float4*)&Qs[kk][ty * 8];
            *(float4*)(a + 4) = *(const float4*)&Qs[kk][ty * 8 + 4];
            *(float4*)(b)     = *(const float4*)&Ks[kk][tx * 8];
            *(float4*)(b + 4) = *(const float4*)&Ks[kk][tx * 8 + 4];
#pragma unroll
            for (int i = 0; i < 8; ++i)
#pragma unroll
                for (int j = 0; j < 8; ++j)
                    acc[i][j] = fmaf(a[i], b[j], acc[i][j]);
        }
    }

#pragma unroll
    for (int i = 0; i < 8; ++i) {
        const int qn = q0 + ty * 8 + i;
        float* srow = S + ((size_t)hb * NN + qn) * NN + k0 + tx * 8;
        *(float4*)(srow)     = make_float4(acc[i][0], acc[i][1], acc[i][2], acc[i][3]);
        *(float4*)(srow + 4) = make_float4(acc[i][4], acc[i][5], acc[i][6], acc[i][7]);
    }
}

// ---------------- exact top-32 + softmax + sparse attn@V (radix-256 select) ----------------
// grid = (N, HB), block = 256. One query row per block. Vectorized S read.
__device__ __forceinline__ float key_to_val(unsigned k) {
    unsigned u = (k & 0x80000000u) ? (k & 0x7fffffffu) : ~k;
    return __uint_as_float(u);
}
__device__ __forceinline__ unsigned val_to_key(unsigned u) {
    return (u & 0x80000000u) ? ~u : (u | 0x80000000u);
}

__global__ void topk_attn_kernel(const float* __restrict__ S, const float* __restrict__ Vp,
                                 float* __restrict__ Op)
{
    const int qn = blockIdx.x;
    const int hb = blockIdx.y;
    const int tid = threadIdx.x;   // 256
    const float* srow = S + ((size_t)hb * NN + qn) * NN;

    __shared__ unsigned skey[NN];
    __shared__ unsigned hist[256];
    __shared__ unsigned kred[8];
    __shared__ int      sh_digit, sh_need;
    __shared__ int      nsel, neq;
    __shared__ int      idxs[TOPK];
    __shared__ float    ws[TOPK];
    __shared__ int      eqidx[64];
    __shared__ float    mxsh, invsh;
    __shared__ float    vacc[4][HD];

    // load row (one float4 per thread), build keys, track max key
    const uint4 uv = *(const uint4*)(srow + (tid << 2));
    unsigned k0 = val_to_key(uv.x), k1 = val_to_key(uv.y);
    unsigned k2 = val_to_key(uv.z), k3 = val_to_key(uv.w);
    *(uint4*)&skey[tid << 2] = make_uint4(k0, k1, k2, k3);
    unsigned lmk = max(max(k0, k1), max(k2, k3));
#pragma unroll
    for (int o = 16; o; o >>= 1) lmk = max(lmk, __shfl_xor_sync(0xffffffffu, lmk, o));
    if ((tid & 31) == 0) kred[tid >> 5] = lmk;
    if (tid == 0) { nsel = 0; neq = 0; }
    __syncthreads();
    if (tid == 0) {
        unsigned m = 0;
#pragma unroll
        for (int w = 0; w < 8; ++w) m = max(m, kred[w]);
        mxsh = key_to_val(m);
    }

    // 4-pass radix-256 selection of the 32nd-largest key
    unsigned pfx = 0;
    int need = TOPK;
#pragma unroll
    for (int pass = 0; pass < 4; ++pass) {
        const int shift = 24 - 8 * pass;
        hist[tid] = 0;          // blockDim == 256
        __syncthreads();
        {
            const uint4 kv = *(const uint4*)&skey[tid << 2];
            const unsigned ks[4] = {kv.x, kv.y, kv.z, kv.w};
#pragma unroll
            for (int j = 0; j < 4; ++j) {
                const unsigned k = ks[j];
                const bool match = (pass == 0) || ((k >> (shift + 8)) == pfx);
                if (match) atomicAdd(&hist[(k >> shift) & 255], 1u);
            }
        }
        __syncthreads();
        if (tid < 32) {
            const int base = tid << 3;
            int loc[8];
            int lsum = 0;
#pragma unroll
            for (int j = 0; j < 8; ++j) { loc[j] = (int)hist[base + j]; lsum += loc[j]; }
            // suffix sum across lanes: suf = sum over lanes >= tid
            int suf = lsum;
#pragma unroll
            for (int o = 1; o < 32; o <<= 1) {
                int v = __shfl_down_sync(0xffffffffu, suf, o);
                if (tid + o < 32) suf += v;
            }
            int sufnext = __shfl_down_sync(0xffffffffu, suf, 1);
            if (tid == 31) sufnext = 0;
            if (suf >= need && sufnext < need) {
                int acc = sufnext;
                int digit = 0;
#pragma unroll
                for (int j = 7; j >= 0; --j) {
                    acc += loc[j];
                    if (acc >= need) { digit = j; break; }
                }
                sh_digit = base + digit;
                sh_need  = need - (acc - loc[digit]);   // #tied-at-boundary to keep
            }
        }
        __syncthreads();
        pfx = (pfx << 8) | (unsigned)sh_digit;
        need = sh_need;
        __syncthreads();
    }
    const unsigned tau = pfx;   // exact key of the 32nd-largest; take `need` ties by index

    const float mx = mxsh;
    // gather: strictly-greater always selected; equals collected for index-tiebreak
    {
        const uint4 kv = *(const uint4*)&skey[tid << 2];
        const unsigned ks[4] = {kv.x, kv.y, kv.z, kv.w};
#pragma unroll
        for (int j = 0; j < 4; ++j) {
            const unsigned k = ks[j];
            const int i = (tid << 2) + j;
            if (k > tau) {
                int p = atomicAdd(&nsel, 1);
                idxs[p] = i;
                ws[p] = expf(key_to_val(k) - mx);
            } else if (k == tau) {
                int p = atomicAdd(&neq, 1);
                if (p < 64) eqidx[p] = i;
            }
        }
    }
    __syncthreads();
    if (tid == 0) {
        const int g = nsel;                 // == TOPK - need
        int e = neq; if (e > 64) e = 64;
        // insertion sort equals by index ascending (e is tiny, usually 1)
        for (int a = 1; a < e; ++a) {
            int v = eqidx[a]; int p2 = a - 1;
            while (p2 >= 0 && eqidx[p2] > v) { eqidx[p2 + 1] = eqidx[p2]; --p2; }
            eqidx[p2 + 1] = v;
        }
        const float wt = expf(key_to_val(tau) - mx);
        for (int a = 0; a < need; ++a) {
            idxs[g + a] = eqidx[a];
            ws[g + a] = wt;
        }
        float wsum = 0.0f;
        for (int a = 0; a < TOPK; ++a) wsum += ws[a];
        invsh = 1.0f / wsum;
    }
    __syncthreads();

    // attn @ V: 4 groups of 64 threads, each group accumulates 8 selected rows
    const float* vb = Vp + (size_t)hb * NN * HD;
    const int d = tid & 63;
    const int grp = tid >> 6;        // 0..3
    {
        float acc = 0.0f;
#pragma unroll
        for (int j = 0; j < 8; ++j) {
            const int sel = (grp << 3) + j;
            acc = fmaf(ws[sel], vb[(size_t)idxs[sel] * HD + d], acc);
        }
        vacc[grp][d] = acc;
    }
    __syncthreads();
    if (tid < HD) {
        const float inv = invsh;
        float acc = vacc[0][tid] + vacc[1][tid] + vacc[2][tid] + vacc[3][tid];
        Op[((size_t)hb * NN + qn) * HD + tid] = acc * inv;
    }
}

// ---------------- residual add + LayerNorm ----------------
// grid = M (8192), block = 256. add is either head-major packed [hb,n,d] or plain [m, D].
__global__ void addnorm_kernel(const float* __restrict__ base, const float* __restrict__ add,
                               const float* __restrict__ gamma, const float* __restrict__ beta,
                               float* __restrict__ out, int add_head_major)
{
    const int m = blockIdx.x;
    const int b = m >> 10, n = m & 1023;
    const int tid = threadIdx.x;   // 256

    __shared__ float buf[DD];
    __shared__ float r1[8], r2[8];
    __shared__ float stats[2];

    float s1 = 0.0f, s2 = 0.0f;
    for (int j = tid; j < DD; j += 256) {
        float av;
        if (add_head_major) {
            const int h = j >> 6, d = j & 63;
            av = add[(((size_t)(h * BB + b) * NN) + n) * HD + d];
        } else {
            av = add[(size_t)m * DD + j];
        }
        const float v = base[(size_t)m * DD + j] + av;
        buf[j] = v;
        s1 += v;
        s2 += v * v;
    }
#pragma unroll
    for (int o = 16; o; o >>= 1) {
        s1 += __shfl_xor_sync(0xffffffffu, s1, o);
        s2 += __shfl_xor_sync(0xffffffffu, s2, o);
    }
    if ((tid & 31) == 0) { r1[tid >> 5] = s1; r2[tid >> 5] = s2; }
    __syncthreads();
    if (tid == 0) {
        float t1 = 0.0f, t2 = 0.0f;
        for (int w = 0; w < 8; ++w) { t1 += r1[w]; t2 += r2[w]; }
        const float mu = t1 / (float)DD;
        const float var = t2 / (float)DD - mu * mu;
        stats[0] = mu;
        stats[1] = rsqrtf(var + 1e-5f);
    }
    __syncthreads();
    const float mu = stats[0], ivs = stats[1];
    for (int j = tid; j < DD; j += 256)
        out[(size_t)m * DD + j] = (buf[j] - mu) * ivs * gamma[j] + beta[j];
}

// ---------------- launch ----------------
extern "C" void kernel_launch(void* const* d_in, const int* in_sizes, int n_in,
                              void* d_out, int out_size)
{
    const float* src = (const float*)d_in[0];
    const float* tgt = (const float*)d_in[1];
    const float* Wq  = (const float*)d_in[2];
    const float* bq  = (const float*)d_in[3];
    const float* Wk  = (const float*)d_in[4];
    const float* bk  = (const float*)d_in[5];
    const float* Wv  = (const float*)d_in[6];
    const float* bv  = (const float*)d_in[7];
    const float* W1  = (const float*)d_in[8];
    const float* b1  = (const float*)d_in[9];
    const float* W2  = (const float*)d_in[10];
    const float* b2  = (const float*)d_in[11];
    const float* g1  = (const float*)d_in[12];
    const float* be1 = (const float*)d_in[13];
    const float* g2  = (const float*)d_in[14];
    const float* be2 = (const float*)d_in[15];
    float* out = (float*)d_out;

    float *Qp, *Kp, *Vp, *S, *Op, *X, *Hh, *F;
    cudaGetSymbolAddress((void**)&Qp, g_Qp);
    cudaGetSymbolAddress((void**)&Kp, g_Kp);
    cudaGetSymbolAddress((void**)&Vp, g_Vp);
    cudaGetSymbolAddress((void**)&S,  g_S);
    cudaGetSymbolAddress((void**)&Op, g_Op);
    cudaGetSymbolAddress((void**)&X,  g_X);
    cudaGetSymbolAddress((void**)&Hh, g_H);
    cudaGetSymbolAddress((void**)&F,  g_F);

    const float qscale = 0.04419417382415922f;   // 1/sqrt(512)

    dim3 gproj(DD / 64, MM / 64);   // (8, 128)

    // QKV projections (head-major packed outputs)
    gemm_kernel<<<gproj, 256>>>(tgt, Wq, bq, Qp, DD, qscale, 0, 1);
    gemm_kernel<<<gproj, 256>>>(src, Wk, bk, Kp, DD, 1.0f,   0, 1);
    gemm_kernel<<<gproj, 256>>>(src, Wv, bv, Vp, DD, 1.0f,   0, 1);

    // scores (128x128 tiles)
    scores_kernel<<<dim3(NN / 128, NN / 128, HB), 256>>>(Qp, Kp, S);

    // exact top-32 + softmax + sparse attn @ V (radix select)
    topk_attn_kernel<<<dim3(NN, HB), 256>>>(S, Vp, Op);

    // residual + LN1
    addnorm_kernel<<<MM, 256>>>(tgt, Op, g1, be1, X, 1);

    // feed-forward
    gemm_kernel<<<gproj, 256>>>(X,  W1, b1, Hh, DD, 1.0f, 1, 0);
    gemm_kernel<<<gproj, 256>>>(Hh, W2, b2, F,  DD, 1.0f, 0, 0);

    // residual + LN2 -> output
    addnorm_kernel<<<MM, 256>>>(X, F, g2, be2, out, 0);
}

// round 15
// speedup vs baseline: 1.1454x; 1.0263x over previous
#include <cuda_runtime.h>
#include <cuda_bf16.h>
#include <math.h>

// Problem constants
#define BB 8
#define NN 1024
#define DD 512
#define HH 8
#define HD 64
#define HB (HH * BB)       // 64
#define MM (BB * NN)       // 8192
#define TOPK 32

// ---------------- scratch (device globals: no allocations allowed) ----------------
__device__ float g_Qp[(size_t)HB * NN * HD];   // 16 MB, head-major packed [hb, n, d]
__device__ float g_Kp[(size_t)HB * NN * HD];   // 16 MB
__device__ float g_Vp[(size_t)HB * NN * HD];   // 16 MB
__device__ float g_S [(size_t)HB * NN * NN];   // 256 MB scores
__device__ float g_Op[(size_t)HB * NN * HD];   // 16 MB attention output (head-major)
__device__ float g_X [(size_t)MM * DD];        // 16 MB after LN1
__device__ float g_H [(size_t)MM * DD];        // 16 MB relu hidden
__device__ float g_F [(size_t)MM * DD];        // 16 MB FF output

// ---------------- fp32 GEMM (64x64 tile, 4x4/thread, double-buffered) ----------------
// grid = (Ndim/64, M/64), block = 256 threads, BK=16
__global__ void gemm_kernel(const float* __restrict__ A, const float* __restrict__ W,
                            const float* __restrict__ bias, float* __restrict__ C,
                            int Kdim, float scale, int relu, int head_major)
{
    const int Ndim = gridDim.x * 64;
    const int row0 = blockIdx.y * 64;
    const int col0 = blockIdx.x * 64;

    __shared__ float As[2][16][64];
    __shared__ float Bs[2][16][64];

    const int tid = threadIdx.x;
    const int tx = tid & 15;
    const int ty = tid >> 4;

    const int lr = tid >> 2;             // 0..63 (A tile row)
    const int lc = (tid & 3) << 2;       // 0,4,8,12
    const int wr = tid >> 4;             // 0..15 (W tile row)
    const int wc = (tid & 15) << 2;      // 0..60

    const float* Aptr = A + (size_t)(row0 + lr) * Kdim + lc;
    const float* Wptr = W + (size_t)wr * Ndim + col0 + wc;

    // prologue: load tile 0 into buffer 0
    {
        float4 av = *(const float4*)(Aptr);
        float4 wv = *(const float4*)(Wptr);
        As[0][lc + 0][lr] = av.x;
        As[0][lc + 1][lr] = av.y;
        As[0][lc + 2][lr] = av.z;
        As[0][lc + 3][lr] = av.w;
        *(float4*)&Bs[0][wr][wc] = wv;
    }
    __syncthreads();

    float acc[4][4] = {};
    int buf = 0;

    for (int kt = 0; kt < Kdim; kt += 16) {
        const bool hn = (kt + 16) < Kdim;
        float4 av, wv;
        if (hn) {
            av = *(const float4*)(Aptr + kt + 16);
            wv = *(const float4*)(Wptr + (size_t)(kt + 16) * Ndim);
        }
#pragma unroll
        for (int kk = 0; kk < 16; ++kk) {
            float a[4], b[4];
#pragma unroll
            for (int i = 0; i < 4; ++i) a[i] = As[buf][kk][(ty << 2) + i];
#pragma unroll
            for (int j = 0; j < 4; ++j) b[j] = Bs[buf][kk][(tx << 2) + j];
#pragma unroll
            for (int i = 0; i < 4; ++i)
#pragma unroll
                for (int j = 0; j < 4; ++j)
                    acc[i][j] = fmaf(a[i], b[j], acc[i][j]);
        }
        if (hn) {
            const int nb = buf ^ 1;
            As[nb][lc + 0][lr] = av.x;
            As[nb][lc + 1][lr] = av.y;
            As[nb][lc + 2][lr] = av.z;
            As[nb][lc + 3][lr] = av.w;
            *(float4*)&Bs[nb][wr][wc] = wv;
            __syncthreads();
            buf = nb;
        }
    }

#pragma unroll
    for (int i = 0; i < 4; ++i) {
        const int row = row0 + (ty << 2) + i;
#pragma unroll
        for (int j = 0; j < 4; ++j) {
            const int col = col0 + (tx << 2) + j;
            float v = (acc[i][j] + bias[col]) * scale;
            if (relu) v = fmaxf(v, 0.0f);
            if (head_major) {
                const int h = col >> 6, d = col & 63;
                const int b = row >> 10, n = row & 1023;   // N = 1024
                C[(((size_t)(h * BB + b) * NN) + n) * HD + d] = v;
            } else {
                C[(size_t)row * Ndim + col] = v;
            }
        }
    }
}

// ---------------- batched scores (128x128 tile, 8x8/thread, BK=32 resident) ----------------
// grid = (8, 8, 64), block = 256; 2 k-phases of 32, front-batched loads
__global__ void scores_kernel(const float* __restrict__ Qp, const float* __restrict__ Kp,
                              float* __restrict__ S)
{
    const int hb = blockIdx.z;
    const int q0 = blockIdx.y * 128;
    const int k0 = blockIdx.x * 128;
    const float* Qb = Qp + (size_t)hb * NN * HD;
    const float* Kb = Kp + (size_t)hb * NN * HD;

    __shared__ float Qs[32][128];   // Qs[d][q]
    __shared__ float Ks[32][128];   // Ks[d][k]

    const int tid = threadIdx.x;
    const int tx = tid & 15;
    const int ty = tid >> 4;
    const int ra0 = tid >> 2;              // 0..63
    const int ca  = (tid & 3) << 2;        // 0,4,8,12

    float acc[8][8] = {};

    for (int kp = 0; kp < HD; kp += 32) {
        if (kp) __syncthreads();           // protect smem reuse across phases
        // front-batched loads for this 32-wide k-phase (8 LDG.128 for Q, 8 for K)
#pragma unroll
        for (int kt = 0; kt < 32; kt += 16) {
            float4 qv0 = *(const float4*)(Qb + (size_t)(q0 + ra0)      * HD + kp + kt + ca);
            float4 qv1 = *(const float4*)(Qb + (size_t)(q0 + ra0 + 64) * HD + kp + kt + ca);
            float4 kv0 = *(const float4*)(Kb + (size_t)(k0 + ra0)      * HD + kp + kt + ca);
            float4 kv1 = *(const float4*)(Kb + (size_t)(k0 + ra0 + 64) * HD + kp + kt + ca);
            Qs[kt + ca + 0][ra0] = qv0.x; Qs[kt + ca + 1][ra0] = qv0.y;
            Qs[kt + ca + 2][ra0] = qv0.z; Qs[kt + ca + 3][ra0] = qv0.w;
            Qs[kt + ca + 0][ra0 + 64] = qv1.x; Qs[kt + ca + 1][ra0 + 64] = qv1.y;
            Qs[kt + ca + 2][ra0 + 64] = qv1.z; Qs[kt + ca + 3][ra0 + 64] = qv1.w;
            Ks[kt + ca + 0][ra0] = kv0.x; Ks[kt + ca + 1][ra0] = kv0.y;
            Ks[kt + ca + 2][ra0] = kv0.z; Ks[kt + ca + 3][ra0] = kv0.w;
            Ks[kt + ca + 0][ra0 + 64] = kv1.x; Ks[kt + ca + 1][ra0 + 64] = kv1.y;
            Ks[kt + ca + 2][ra0 + 64] = kv1.z; Ks[kt + ca + 3][ra0 + 64] = kv1.w;
        }
        __syncthreads();
#pragma unroll 16
        for (int kk = 0; kk < 32; ++kk) {
            float a[8], b[8];
            *(float4*)(a)     = *(const float4*)&Qs[kk][ty * 8];
            *(float4*)(a + 4) = *(const float4*)&Qs[kk][ty * 8 + 4];
            *(float4*)(b)     = *(const float4*)&Ks[kk][tx * 8];
            *(float4*)(b + 4) = *(const float4*)&Ks[kk][tx * 8 + 4];
#pragma unroll
            for (int i = 0; i < 8; ++i)
#pragma unroll
                for (int j = 0; j < 8; ++j)
                    acc[i][j] = fmaf(a[i], b[j], acc[i][j]);
        }
    }

#pragma unroll
    for (int i = 0; i < 8; ++i) {
        const int qn = q0 + ty * 8 + i;
        float* srow = S + ((size_t)hb * NN + qn) * NN + k0 + tx * 8;
        *(float4*)(srow)     = make_float4(acc[i][0], acc[i][1], acc[i][2], acc[i][3]);
        *(float4*)(srow + 4) = make_float4(acc[i][4], acc[i][5], acc[i][6], acc[i][7]);
    }
}

// ---------------- exact top-32 + softmax + sparse attn@V (radix-256 select) ----------------
// grid = (N, HB), block = 256. One query row per block. Vectorized S read.
__device__ __forceinline__ float key_to_val(unsigned k) {
    unsigned u = (k & 0x80000000u) ? (k & 0x7fffffffu) : ~k;
    return __uint_as_float(u);
}
__device__ __forceinline__ unsigned val_to_key(unsigned u) {
    return (u & 0x80000000u) ? ~u : (u | 0x80000000u);
}

__global__ void topk_attn_kernel(const float* __restrict__ S, const float* __restrict__ Vp,
                                 float* __restrict__ Op)
{
    const int qn = blockIdx.x;
    const int hb = blockIdx.y;
    const int tid = threadIdx.x;   // 256
    const float* srow = S + ((size_t)hb * NN + qn) * NN;

    __shared__ unsigned skey[NN];
    __shared__ unsigned hist[256];
    __shared__ unsigned kred[8];
    __shared__ int      sh_digit, sh_need;
    __shared__ int      nsel, neq;
    __shared__ int      idxs[TOPK];
    __shared__ float    ws[TOPK];
    __shared__ int      eqidx[64];
    __shared__ float    mxsh, invsh;
    __shared__ float    vacc[4][HD];

    // load row (one float4 per thread), build keys, track max key
    const uint4 uv = *(const uint4*)(srow + (tid << 2));
    unsigned k0 = val_to_key(uv.x), k1 = val_to_key(uv.y);
    unsigned k2 = val_to_key(uv.z), k3 = val_to_key(uv.w);
    *(uint4*)&skey[tid << 2] = make_uint4(k0, k1, k2, k3);
    unsigned lmk = max(max(k0, k1), max(k2, k3));
#pragma unroll
    for (int o = 16; o; o >>= 1) lmk = max(lmk, __shfl_xor_sync(0xffffffffu, lmk, o));
    if ((tid & 31) == 0) kred[tid >> 5] = lmk;
    if (tid == 0) { nsel = 0; neq = 0; }
    __syncthreads();
    if (tid == 0) {
        unsigned m = 0;
#pragma unroll
        for (int w = 0; w < 8; ++w) m = max(m, kred[w]);
        mxsh = key_to_val(m);
    }

    // 4-pass radix-256 selection of the 32nd-largest key
    unsigned pfx = 0;
    int need = TOPK;
#pragma unroll
    for (int pass = 0; pass < 4; ++pass) {
        const int shift = 24 - 8 * pass;
        hist[tid] = 0;          // blockDim == 256
        __syncthreads();
        {
            const uint4 kv = *(const uint4*)&skey[tid << 2];
            const unsigned ks[4] = {kv.x, kv.y, kv.z, kv.w};
#pragma unroll
            for (int j = 0; j < 4; ++j) {
                const unsigned k = ks[j];
                const bool match = (pass == 0) || ((k >> (shift + 8)) == pfx);
                if (match) atomicAdd(&hist[(k >> shift) & 255], 1u);
            }
        }
        __syncthreads();
        if (tid < 32) {
            const int base = tid << 3;
            int loc[8];
            int lsum = 0;
#pragma unroll
            for (int j = 0; j < 8; ++j) { loc[j] = (int)hist[base + j]; lsum += loc[j]; }
            // suffix sum across lanes: suf = sum over lanes >= tid
            int suf = lsum;
#pragma unroll
            for (int o = 1; o < 32; o <<= 1) {
                int v = __shfl_down_sync(0xffffffffu, suf, o);
                if (tid + o < 32) suf += v;
            }
            int sufnext = __shfl_down_sync(0xffffffffu, suf, 1);
            if (tid == 31) sufnext = 0;
            if (suf >= need && sufnext < need) {
                int acc = sufnext;
                int digit = 0;
#pragma unroll
                for (int j = 7; j >= 0; --j) {
                    acc += loc[j];
                    if (acc >= need) { digit = j; break; }
                }
                sh_digit = base + digit;
                sh_need  = need - (acc - loc[digit]);   // #tied-at-boundary to keep
            }
        }
        __syncthreads();
        pfx = (pfx << 8) | (unsigned)sh_digit;
        need = sh_need;
        __syncthreads();
    }
    const unsigned tau = pfx;   // exact key of the 32nd-largest; take `need` ties by index

    const float mx = mxsh;
    // gather: strictly-greater always selected; equals collected for index-tiebreak
    {
        const uint4 kv = *(const uint4*)&skey[tid << 2];
        const unsigned ks[4] = {kv.x, kv.y, kv.z, kv.w};
#pragma unroll
        for (int j = 0; j < 4; ++j) {
            const unsigned k = ks[j];
            const int i = (tid << 2) + j;
            if (k > tau) {
                int p = atomicAdd(&nsel, 1);
                idxs[p] = i;
                ws[p] = expf(key_to_val(k) - mx);
            } else if (k == tau) {
                int p = atomicAdd(&neq, 1);
                if (p < 64) eqidx[p] = i;
            }
        }
    }
    __syncthreads();
    if (tid == 0) {
        const int g = nsel;                 // == TOPK - need
        int e = neq; if (e > 64) e = 64;
        // insertion sort equals by index ascending (e is tiny, usually 1)
        for (int a = 1; a < e; ++a) {
            int v = eqidx[a]; int p2 = a - 1;
            while (p2 >= 0 && eqidx[p2] > v) { eqidx[p2 + 1] = eqidx[p2]; --p2; }
            eqidx[p2 + 1] = v;
        }
        const float wt = expf(key_to_val(tau) - mx);
        for (int a = 0; a < need; ++a) {
            idxs[g + a] = eqidx[a];
            ws[g + a] = wt;
        }
        float wsum = 0.0f;
        for (int a = 0; a < TOPK; ++a) wsum += ws[a];
        invsh = 1.0f / wsum;
    }
    __syncthreads();

    // attn @ V: 4 groups of 64 threads, each group accumulates 8 selected rows
    const float* vb = Vp + (size_t)hb * NN * HD;
    const int d = tid & 63;
    const int grp = tid >> 6;        // 0..3
    {
        float acc = 0.0f;
#pragma unroll
        for (int j = 0; j < 8; ++j) {
            const int sel = (grp << 3) + j;
            acc = fmaf(ws[sel], vb[(size_t)idxs[sel] * HD + d], acc);
        }
        vacc[grp][d] = acc;
    }
    __syncthreads();
    if (tid < HD) {
        const float inv = invsh;
        float acc = vacc[0][tid] + vacc[1][tid] + vacc[2][tid] + vacc[3][tid];
        Op[((size_t)hb * NN + qn) * HD + tid] = acc * inv;
    }
}

// ---------------- residual add + LayerNorm ----------------
// grid = M (8192), block = 256. add is either head-major packed [hb,n,d] or plain [m, D].
__global__ void addnorm_kernel(const float* __restrict__ base, const float* __restrict__ add,
                               const float* __restrict__ gamma, const float* __restrict__ beta,
                               float* __restrict__ out, int add_head_major)
{
    const int m = blockIdx.x;
    const int b = m >> 10, n = m & 1023;
    const int tid = threadIdx.x;   // 256

    __shared__ float buf[DD];
    __shared__ float r1[8], r2[8];
    __shared__ float stats[2];

    float s1 = 0.0f, s2 = 0.0f;
    for (int j = tid; j < DD; j += 256) {
        float av;
        if (add_head_major) {
            const int h = j >> 6, d = j & 63;
            av = add[(((size_t)(h * BB + b) * NN) + n) * HD + d];
        } else {
            av = add[(size_t)m * DD + j];
        }
        const float v = base[(size_t)m * DD + j] + av;
        buf[j] = v;
        s1 += v;
        s2 += v * v;
    }
#pragma unroll
    for (int o = 16; o; o >>= 1) {
        s1 += __shfl_xor_sync(0xffffffffu, s1, o);
        s2 += __shfl_xor_sync(0xffffffffu, s2, o);
    }
    if ((tid & 31) == 0) { r1[tid >> 5] = s1; r2[tid >> 5] = s2; }
    __syncthreads();
    if (tid == 0) {
        float t1 = 0.0f, t2 = 0.0f;
        for (int w = 0; w < 8; ++w) { t1 += r1[w]; t2 += r2[w]; }
        const float mu = t1 / (float)DD;
        const float var = t2 / (float)DD - mu * mu;
        stats[0] = mu;
        stats[1] = rsqrtf(var + 1e-5f);
    }
    __syncthreads();
    const float mu = stats[0], ivs = stats[1];
    for (int j = tid; j < DD; j += 256)
        out[(size_t)m * DD + j] = (buf[j] - mu) * ivs * gamma[j] + beta[j];
}

// ---------------- launch ----------------
extern "C" void kernel_launch(void* const* d_in, const int* in_sizes, int n_in,
                              void* d_out, int out_size)
{
    const float* src = (const float*)d_in[0];
    const float* tgt = (const float*)d_in[1];
    const float* Wq  = (const float*)d_in[2];
    const float* bq  = (const float*)d_in[3];
    const float* Wk  = (const float*)d_in[4];
    const float* bk  = (const float*)d_in[5];
    const float* Wv  = (const float*)d_in[6];
    const float* bv  = (const float*)d_in[7];
    const float* W1  = (const float*)d_in[8];
    const float* b1  = (const float*)d_in[9];
    const float* W2  = (const float*)d_in[10];
    const float* b2  = (const float*)d_in[11];
    const float* g1  = (const float*)d_in[12];
    const float* be1 = (const float*)d_in[13];
    const float* g2  = (const float*)d_in[14];
    const float* be2 = (const float*)d_in[15];
    float* out = (float*)d_out;

    float *Qp, *Kp, *Vp, *S, *Op, *X, *Hh, *F;
    cudaGetSymbolAddress((void**)&Qp, g_Qp);
    cudaGetSymbolAddress((void**)&Kp, g_Kp);
    cudaGetSymbolAddress((void**)&Vp, g_Vp);
    cudaGetSymbolAddress((void**)&S,  g_S);
    cudaGetSymbolAddress((void**)&Op, g_Op);
    cudaGetSymbolAddress((void**)&X,  g_X);
    cudaGetSymbolAddress((void**)&Hh, g_H);
    cudaGetSymbolAddress((void**)&F,  g_F);

    const float qscale = 0.04419417382415922f;   // 1/sqrt(512)

    dim3 gproj(DD / 64, MM / 64);   // (8, 128)

    // QKV projections (head-major packed outputs)
    gemm_kernel<<<gproj, 256>>>(tgt, Wq, bq, Qp, DD, qscale, 0, 1);
    gemm_kernel<<<gproj, 256>>>(src, Wk, bk, Kp, DD, 1.0f,   0, 1);
    gemm_kernel<<<gproj, 256>>>(src, Wv, bv, Vp, DD, 1.0f,   0, 1);

    // scores (128x128 tiles, BK=32 resident)
    scores_kernel<<<dim3(NN / 128, NN / 128, HB), 256>>>(Qp, Kp, S);

    // exact top-32 + softmax + sparse attn @ V (radix select)
    topk_attn_kernel<<<dim3(NN, HB), 256>>>(S, Vp, Op);

    // residual + LN1
    addnorm_kernel<<<MM, 256>>>(tgt, Op, g1, be1, X, 1);

    // feed-forward
    gemm_kernel<<<gproj, 256>>>(X,  W1, b1, Hh, DD, 1.0f, 1, 0);
    gemm_kernel<<<gproj, 256>>>(Hh, W2, b2, F,  DD, 1.0f, 0, 0);

    // residual + LN2 -> output
    addnorm_kernel<<<MM, 256>>>(X, F, g2, be2, out, 0);
}